// round 2
// baseline (speedup 1.0000x reference)
#include <cuda_runtime.h>
#include <cuda_bf16.h>

#define CIN 128
#define CH  64
#define MAXN 100000
#define MAXG 512

// Scratch (allocation-free rule: __device__ globals)
__device__ __align__(16) float g_dis[MAXN];
__device__ __align__(16) float g_h[(size_t)MAXN * CH];
__device__ __align__(16) float g_agg[(size_t)MAXN * CH];
__device__ float g_gsum[MAXG];
__device__ float g_gcnt[MAXG];

// ---------------------------------------------------------------------------
// K0: init deg=1 (self loop), zero graph accumulators
__global__ void k_init(int N, int G) {
    int i = blockIdx.x * blockDim.x + threadIdx.x;
    if (i < N) g_dis[i] = 1.0f;
    if (i < G) { g_gsum[i] = 0.0f; g_gcnt[i] = 0.0f; }
}

// K1: degree count at dst
__global__ void k_degree(const int* __restrict__ dst, int E) {
    int e = blockIdx.x * blockDim.x + threadIdx.x;
    if (e < E) atomicAdd(&g_dis[dst[e]], 1.0f);
}

// K2: dis = rsqrt(deg)  (deg >= 1 always)
__global__ void k_rsqrt(int N) {
    int i = blockIdx.x * blockDim.x + threadIdx.x;
    if (i < N) g_dis[i] = rsqrtf(g_dis[i]);
}

// ---------------------------------------------------------------------------
// K3: h = x @ W1 ; agg = h * dis^2  (self-loop init fused)
// Block: 256 thr = 8 warps, 32 rows/block. Warp -> 4 rows, lane -> 2 cols.
__global__ __launch_bounds__(256) void k_gemm1(
    const float* __restrict__ x, const float* __restrict__ W, int N)
{
    __shared__ float Ws[CIN * CH];       // 32 KB  [k][64]
    __shared__ float xs[32][CIN];        // 16 KB
    int tid = threadIdx.x;
    for (int i = tid; i < CIN * CH; i += 256) Ws[i] = W[i];
    int rowBase = blockIdx.x * 32;
    const float4* x4 = (const float4*)x;
    for (int i = tid; i < 32 * (CIN / 4); i += 256) {
        int r = i / (CIN / 4), c = i % (CIN / 4);
        int row = rowBase + r;
        float4 v = make_float4(0.f, 0.f, 0.f, 0.f);
        if (row < N) v = x4[(size_t)row * (CIN / 4) + c];
        ((float4*)&xs[r][0])[c] = v;
    }
    __syncthreads();

    int warp = tid >> 5, lane = tid & 31;
    int r0 = warp * 4;
    float2 a0 = {0.f,0.f}, a1 = {0.f,0.f}, a2 = {0.f,0.f}, a3 = {0.f,0.f};
    const float2* Ws2 = (const float2*)Ws;
#pragma unroll 8
    for (int k = 0; k < CIN; k++) {
        float2 w = Ws2[k * (CH / 2) + lane];
        float v0 = xs[r0 + 0][k], v1 = xs[r0 + 1][k];
        float v2 = xs[r0 + 2][k], v3 = xs[r0 + 3][k];
        a0.x += v0 * w.x; a0.y += v0 * w.y;
        a1.x += v1 * w.x; a1.y += v1 * w.y;
        a2.x += v2 * w.x; a2.y += v2 * w.y;
        a3.x += v3 * w.x; a3.y += v3 * w.y;
    }
    float2 acc[4] = {a0, a1, a2, a3};
#pragma unroll
    for (int r = 0; r < 4; r++) {
        int row = rowBase + r0 + r;
        if (row < N) {
            float d = g_dis[row]; float d2 = d * d;
            ((float2*)(g_h + (size_t)row * CH))[lane] = acc[r];
            float2 ag; ag.x = acc[r].x * d2; ag.y = acc[r].y * d2;
            ((float2*)(g_agg + (size_t)row * CH))[lane] = ag;
        }
    }
}

// K6: h2 = relu(agg + b1) @ W2 ; epilogue: h = h2, agg = h2 * dis^2
__global__ __launch_bounds__(256) void k_gemm2(
    const float* __restrict__ W, const float* __restrict__ b1, int N)
{
    __shared__ float Ws[CH * CH];        // 16 KB
    __shared__ float xs[32][CH];         //  8 KB
    int tid = threadIdx.x;
    for (int i = tid; i < CH * CH; i += 256) Ws[i] = W[i];
    int rowBase = blockIdx.x * 32;
    for (int i = tid; i < 32 * (CH / 4); i += 256) {
        int r = i / (CH / 4), c = i % (CH / 4);
        int row = rowBase + r;
        float4 v = make_float4(0.f, 0.f, 0.f, 0.f);
        if (row < N) {
            float4 a = ((const float4*)g_agg)[(size_t)row * (CH / 4) + c];
            float4 b = ((const float4*)b1)[c];
            v.x = fmaxf(a.x + b.x, 0.f); v.y = fmaxf(a.y + b.y, 0.f);
            v.z = fmaxf(a.z + b.z, 0.f); v.w = fmaxf(a.w + b.w, 0.f);
        }
        ((float4*)&xs[r][0])[c] = v;
    }
    __syncthreads();

    int warp = tid >> 5, lane = tid & 31;
    int r0 = warp * 4;
    float2 a0 = {0.f,0.f}, a1 = {0.f,0.f}, a2 = {0.f,0.f}, a3 = {0.f,0.f};
    const float2* Ws2 = (const float2*)Ws;
#pragma unroll 8
    for (int k = 0; k < CH; k++) {
        float2 w = Ws2[k * (CH / 2) + lane];
        float v0 = xs[r0 + 0][k], v1 = xs[r0 + 1][k];
        float v2 = xs[r0 + 2][k], v3 = xs[r0 + 3][k];
        a0.x += v0 * w.x; a0.y += v0 * w.y;
        a1.x += v1 * w.x; a1.y += v1 * w.y;
        a2.x += v2 * w.x; a2.y += v2 * w.y;
        a3.x += v3 * w.x; a3.y += v3 * w.y;
    }
    float2 acc[4] = {a0, a1, a2, a3};
#pragma unroll
    for (int r = 0; r < 4; r++) {
        int row = rowBase + r0 + r;
        if (row < N) {
            float d = g_dis[row]; float d2 = d * d;
            ((float2*)(g_h + (size_t)row * CH))[lane] = acc[r];
            float2 ag; ag.x = acc[r].x * d2; ag.y = acc[r].y * d2;
            ((float2*)(g_agg + (size_t)row * CH))[lane] = ag;
        }
    }
}

// ---------------------------------------------------------------------------
// K5/K8: edge scatter. 16 lanes per edge, float4 gather + red.v4 scatter-add.
__global__ __launch_bounds__(256) void k_scatter(
    const int* __restrict__ src, const int* __restrict__ dst, int E)
{
    int tid = blockIdx.x * blockDim.x + threadIdx.x;
    int e = tid >> 4, l = tid & 15;
    if (e >= E) return;
    int s = src[e], d = dst[e];
    float nm = g_dis[s] * g_dis[d];
    float4 v = ((const float4*)g_h)[(size_t)s * (CH / 4) + l];
    float* p = g_agg + (size_t)d * CH + l * 4;
    asm volatile("red.global.add.v4.f32 [%0], {%1,%2,%3,%4};"
                 :: "l"(p), "f"(v.x * nm), "f"(v.y * nm),
                    "f"(v.z * nm), "f"(v.w * nm) : "memory");
}

// ---------------------------------------------------------------------------
// K9: per-node s = relu(agg2 + b2) . Wl  -> segment sum per graph
__global__ __launch_bounds__(256) void k_pool(
    const int* __restrict__ batch, const float* __restrict__ b2,
    const float* __restrict__ Wl, int N)
{
    int tid = blockIdx.x * blockDim.x + threadIdx.x;
    int n = tid >> 4, l = tid & 15;
    if (n >= N) return;
    float4 v = ((const float4*)g_agg)[(size_t)n * (CH / 4) + l];
    float4 b = ((const float4*)b2)[l];
    float4 w = ((const float4*)Wl)[l];
    float s = fmaxf(v.x + b.x, 0.f) * w.x + fmaxf(v.y + b.y, 0.f) * w.y
            + fmaxf(v.z + b.z, 0.f) * w.z + fmaxf(v.w + b.w, 0.f) * w.w;
    s += __shfl_down_sync(0xffffffffu, s, 8, 16);
    s += __shfl_down_sync(0xffffffffu, s, 4, 16);
    s += __shfl_down_sync(0xffffffffu, s, 2, 16);
    s += __shfl_down_sync(0xffffffffu, s, 1, 16);
    if (l == 0) {
        int g = batch[n];
        atomicAdd(&g_gsum[g], s);
        atomicAdd(&g_gcnt[g], 1.0f);
    }
}

// K10: logits
__global__ void k_logits(float* __restrict__ out, const float* __restrict__ bl, int G) {
    int g = blockIdx.x * blockDim.x + threadIdx.x;
    if (g < G) out[g] = g_gsum[g] / fmaxf(g_gcnt[g], 1.0f) + bl[0];
}

// ---------------------------------------------------------------------------
extern "C" void kernel_launch(void* const* d_in, const int* in_sizes, int n_in,
                              void* d_out, int out_size)
{
    const float* x     = (const float*)d_in[0];
    const int*   ei    = (const int*)  d_in[1];
    const int*   batch = (const int*)  d_in[2];
    const float* W1    = (const float*)d_in[3];
    const float* b1    = (const float*)d_in[4];
    const float* W2    = (const float*)d_in[5];
    const float* b2    = (const float*)d_in[6];
    const float* Wl    = (const float*)d_in[7];
    const float* bl    = (const float*)d_in[8];

    int N = in_sizes[0] / CIN;
    int E = in_sizes[1] / 2;
    int G = out_size;
    const int* src = ei;
    const int* dst = ei + E;
    float* out = (float*)d_out;

    int nb  = (N + 255) / 256;
    int eb  = (E + 255) / 256;
    int gb  = (N + 31) / 32;
    int sb  = (E * 16 + 255) / 256;
    int pb  = (N * 16 + 255) / 256;

    k_init   <<<nb, 256>>>(N, G);
    k_degree <<<eb, 256>>>(dst, E);
    k_rsqrt  <<<nb, 256>>>(N);
    k_gemm1  <<<gb, 256>>>(x, W1, N);
    k_scatter<<<sb, 256>>>(src, dst, E);
    k_gemm2  <<<gb, 256>>>(W2, b1, N);
    k_scatter<<<sb, 256>>>(src, dst, E);
    k_pool   <<<pb, 256>>>(batch, b2, Wl, N);
    k_logits <<<(G + 255) / 256, 256>>>(out, bl, G);
}